// round 8
// baseline (speedup 1.0000x reference)
#include <cuda_runtime.h>
#include <cuda_bf16.h>
#include <stdint.h>

#define N_NODES 100000
#define N_EDGES 1600000
#define M_TOT   (N_EDGES + N_NODES)
#define F_IN    128
#define HID     64
#define NCLS    10
#define NGRAPH  128

// ---------------- device scratch (no allocation allowed) ----------------
__device__ int   g_src[N_EDGES];
__device__ int   g_dst[N_EDGES];
__device__ int   g_deg[N_NODES];
__device__ int   g_rowptr[N_NODES + 1];
__device__ int   g_offs[N_NODES];
__device__ int   g_csr_src[N_EDGES];
__device__ int   g_batch[N_NODES];
__device__ float g_hA[N_NODES * HID];   // gemm output (messages h)
__device__ float g_hB[N_NODES * HID];   // aggregated output
__device__ float g_esrc[N_NODES];
__device__ float g_edst[N_NODES];
__device__ float g_ex[M_TOT];
__device__ float g_pool[NGRAPH * HID];
__device__ float g_cnt[NGRAPH];
__device__ int   g_flags[2];            // [0]: edge idx is int32, [1]: batch is int32

// ---------------- dtype sniffer ----------------
// int64 little-endian values < 2^31 have zero high words at odd 32-bit indices.
// For batch (sorted, starts at 0) probe the tail where values ~ 127.
__global__ void k_detect(const unsigned* __restrict__ ew, const unsigned* __restrict__ bw) {
    int t = threadIdx.x;
    int ae = 0, ab = 0;
    for (int i = t; i < 1024; i += 256) {
        if (ew[2 * i + 1]) ae = 1;
        int w = (N_NODES - 2048) + 2 * i + 1;      // odd, < N_NODES words (safe both dtypes)
        if (bw[w]) ab = 1;
    }
    int e32 = __syncthreads_or(ae);
    int b32 = __syncthreads_or(ab);
    if (t == 0) { g_flags[0] = e32 ? 1 : 0; g_flags[1] = b32 ? 1 : 0; }
}

// zero deg/pool/cnt + convert batch
__global__ void k_init(const void* __restrict__ bbuf) {
    int i = blockIdx.x * blockDim.x + threadIdx.x;
    if (i >= N_NODES) return;
    g_deg[i] = 0;
    g_batch[i] = g_flags[1] ? ((const int*)bbuf)[i]
                            : (int)((const long long*)bbuf)[i];
    if (i < NGRAPH * HID) g_pool[i] = 0.f;
    if (i < NGRAPH)       g_cnt[i]  = 0.f;
}

__global__ void k_convert(const void* __restrict__ ebuf) {
    int e = blockIdx.x * blockDim.x + threadIdx.x;
    if (e >= N_EDGES) return;
    int s, d;
    if (g_flags[0]) {
        const int* p = (const int*)ebuf;
        s = p[e]; d = p[N_EDGES + e];
    } else {
        const long long* p = (const long long*)ebuf;
        s = (int)p[e]; d = (int)p[N_EDGES + e];
    }
    g_src[e] = s; g_dst[e] = d;
    atomicAdd(&g_deg[d], 1);
}

__global__ void k_scan() {
    const int CH = (N_NODES + 1023) / 1024;      // 98
    int t = threadIdx.x;
    int lo = t * CH, hi = min(lo + CH, N_NODES);
    int s = 0;
    for (int i = lo; i < hi; i++) s += g_deg[i];
    __shared__ int sc[1024];
    sc[t] = s; __syncthreads();
    for (int off = 1; off < 1024; off <<= 1) {
        int v = (t >= off) ? sc[t - off] : 0;
        __syncthreads();
        sc[t] += v;
        __syncthreads();
    }
    int run = (t > 0) ? sc[t - 1] : 0;
    for (int i = lo; i < hi; i++) {
        g_rowptr[i] = run; g_offs[i] = run;
        run += g_deg[i];
    }
    if (t == 1023) g_rowptr[N_NODES] = sc[1023];
}

__global__ void k_scatter() {
    int e = blockIdx.x * blockDim.x + threadIdx.x;
    if (e >= N_EDGES) return;
    int d = g_dst[e];
    int pos = atomicAdd(&g_offs[d], 1);
    g_csr_src[pos] = g_src[e];
}

// ---------------- GEMM: H[n,k] = sum_f X[n,f] W[k,f]; also e_src/e_dst ----
// blockDim (64,4): tx = output column k, each thread handles 8 rows.
// 32 rows per block, grid = N/32 (exact).
__global__ void k_gemm(const float* __restrict__ X, const float* __restrict__ W,
                       const float* __restrict__ a_s, const float* __restrict__ a_d,
                       float* __restrict__ Hout, float* __restrict__ esrc,
                       float* __restrict__ edst, int Fin) {
    extern __shared__ float sm[];
    float* W_s = sm;                     // [64][Fin+4]
    float* xs  = sm + 64 * (Fin + 4);    // [32][Fin]
    const int tx = threadIdx.x, ty = threadIdx.y;
    const int tid = ty * 64 + tx;
    const int row0 = blockIdx.x * 32;

    for (int idx = tid; idx < 64 * Fin; idx += 256) {
        int k = idx / Fin, f = idx - k * Fin;
        W_s[k * (Fin + 4) + f] = W[idx];
    }
    for (int idx = tid; idx < 32 * Fin; idx += 256)
        xs[idx] = X[row0 * Fin + idx];
    __syncthreads();

    const float4* Wv = (const float4*)(W_s + tx * (Fin + 4));
    float acc[8];
#pragma unroll
    for (int j = 0; j < 8; j++) acc[j] = 0.f;

    const int F4 = Fin >> 2;
    for (int f4 = 0; f4 < F4; f4++) {
        float4 w = Wv[f4];
#pragma unroll
        for (int j = 0; j < 8; j++) {
            float4 xv = ((const float4*)(xs + (ty * 8 + j) * Fin))[f4];
            acc[j] += xv.x * w.x + xv.y * w.y + xv.z * w.z + xv.w * w.w;
        }
    }

    const float as = a_s[tx], ad = a_d[tx];
    __shared__ float s_ps[32][2], s_pd[32][2];
    const unsigned FULL = 0xffffffffu;
    const int lane = tx & 31, half = tx >> 5;
#pragma unroll
    for (int j = 0; j < 8; j++) {
        int r = ty * 8 + j;
        float ps = acc[j] * as, pd = acc[j] * ad;
#pragma unroll
        for (int o = 16; o; o >>= 1) {
            ps += __shfl_xor_sync(FULL, ps, o);
            pd += __shfl_xor_sync(FULL, pd, o);
        }
        if (lane == 0) { s_ps[r][half] = ps; s_pd[r][half] = pd; }
        Hout[(row0 + r) * HID + tx] = acc[j];
    }
    __syncthreads();
    if (tid < 32)       esrc[row0 + tid]        = s_ps[tid][0] + s_ps[tid][1];
    else if (tid < 64)  edst[row0 + tid - 32]   = s_pd[tid - 32][0] + s_pd[tid - 32][1];
}

// ---------------- fused per-node aggregation (warp per node) ----------------
__global__ void k_agg(const float* __restrict__ Hn, const float* __restrict__ esrc,
                      const float* __restrict__ edst, const float* __restrict__ bias,
                      float* __restrict__ Out, int do_relu) {
    const unsigned FULL = 0xffffffffu;
    const int warp = threadIdx.x >> 5, lane = threadIdx.x & 31;
    const int n = blockIdx.x * 8 + warp;
    const int start = g_rowptr[n], end = g_rowptr[n + 1];
    const int cnt = end - start + 1;                 // + self loop
    const float ed = edst[n];

    // pass 1: scores + max
    float m = -1e30f;
    for (int i = lane; i < cnt; i += 32) {
        int s = (i == cnt - 1) ? n : g_csr_src[start + i];
        float e = esrc[s] + ed;
        e = (e > 0.f) ? e : 0.2f * e;                // leaky relu 0.2
        g_ex[(i == cnt - 1) ? (N_EDGES + n) : (start + i)] = e;
        m = fmaxf(m, e);
    }
#pragma unroll
    for (int o = 16; o; o >>= 1) m = fmaxf(m, __shfl_xor_sync(FULL, m, o));

    // pass 2: exp + sum
    float sum = 0.f;
    for (int i = lane; i < cnt; i += 32) {
        int pos = (i == cnt - 1) ? (N_EDGES + n) : (start + i);
        float v = __expf(g_ex[pos] - m);
        g_ex[pos] = v;
        sum += v;
    }
#pragma unroll
    for (int o = 16; o; o >>= 1) sum += __shfl_xor_sync(FULL, sum, o);
    const float inv = 1.f / sum;

    // pass 3: weighted accumulation, lane owns 2 features
    float ax = 0.f, ay = 0.f;
    for (int base = 0; base < cnt; base += 32) {
        int i = base + lane;
        float v = 0.f; int s = n;
        if (i < cnt) {
            int pos = (i == cnt - 1) ? (N_EDGES + n) : (start + i);
            v = g_ex[pos];
            if (i < cnt - 1) s = g_csr_src[start + i];
        }
        int lim = min(32, cnt - base);
        for (int j = 0; j < lim; j++) {
            float a = __shfl_sync(FULL, v, j);
            int  sj = __shfl_sync(FULL, s, j);
            float2 hv = *(const float2*)(Hn + sj * HID + lane * 2);
            ax += a * hv.x;
            ay += a * hv.y;
        }
    }
    float2 o;
    o.x = ax * inv + bias[lane * 2];
    o.y = ay * inv + bias[lane * 2 + 1];
    if (do_relu) { o.x = fmaxf(o.x, 0.f); o.y = fmaxf(o.y, 0.f); }
    *(float2*)(Out + n * HID + lane * 2) = o;
}

// ---------------- pooling + final linear ----------------
__global__ void k_pool() {
    int idx = blockIdx.x * blockDim.x + threadIdx.x;   // N*32 threads
    int n = idx >> 5, lane = idx & 31;
    if (n >= N_NODES) return;
    int b = g_batch[n];
    float2 hv = *(const float2*)(g_hB + n * HID + lane * 2);
    atomicAdd(&g_pool[b * HID + lane * 2], hv.x);
    atomicAdd(&g_pool[b * HID + lane * 2 + 1], hv.y);
    if (lane == 0) atomicAdd(&g_cnt[b], 1.f);
}

__global__ void k_final(const float* __restrict__ WL, const float* __restrict__ bl,
                        float* __restrict__ out) {
    const unsigned FULL = 0xffffffffu;
    int b = blockIdx.x, lane = threadIdx.x;
    float c = fmaxf(g_cnt[b], 1.f);
    float inv = 1.f / c;
    float v0 = g_pool[b * HID + lane] * inv;
    float v1 = g_pool[b * HID + 32 + lane] * inv;
    for (int ci = 0; ci < NCLS; ci++) {
        float p = v0 * WL[ci * HID + lane] + v1 * WL[ci * HID + 32 + lane];
#pragma unroll
        for (int o = 16; o; o >>= 1) p += __shfl_xor_sync(FULL, p, o);
        if (lane == 0) out[b * NCLS + ci] = p + bl[ci];
    }
}

// ---------------- launch ----------------
extern "C" void kernel_launch(void* const* d_in, const int* in_sizes, int n_in,
                              void* d_out, int out_size) {
    const float* x     = (const float*)d_in[0];
    const void*  ebuf  = d_in[1];
    const void*  bbuf  = d_in[2];
    const float* W1    = (const float*)d_in[3];
    const float* as1   = (const float*)d_in[4];
    const float* ad1   = (const float*)d_in[5];
    const float* b1    = (const float*)d_in[6];
    const float* W2    = (const float*)d_in[7];
    const float* as2   = (const float*)d_in[8];
    const float* ad2   = (const float*)d_in[9];
    const float* b2    = (const float*)d_in[10];
    const float* W3    = (const float*)d_in[11];
    const float* as3   = (const float*)d_in[12];
    const float* ad3   = (const float*)d_in[13];
    const float* b3    = (const float*)d_in[14];
    const float* WL    = (const float*)d_in[15];
    const float* bl    = (const float*)d_in[16];
    float* out = (float*)d_out;

    float *hA, *hB, *esrc, *edst;
    cudaGetSymbolAddress((void**)&hA,   g_hA);
    cudaGetSymbolAddress((void**)&hB,   g_hB);
    cudaGetSymbolAddress((void**)&esrc, g_esrc);
    cudaGetSymbolAddress((void**)&edst, g_edst);

    size_t smem1 = (size_t)(64 * (F_IN + 4) + 32 * F_IN) * 4;   // 50176 B
    size_t smem2 = (size_t)(64 * (HID + 4) + 32 * HID) * 4;     // 25600 B
    static int attr_set = 0;
    if (!attr_set) {
        cudaFuncSetAttribute(k_gemm, cudaFuncAttributeMaxDynamicSharedMemorySize, 65536);
        attr_set = 1;
    }

    // graph preprocessing
    k_detect<<<1, 256>>>((const unsigned*)ebuf, (const unsigned*)bbuf);
    k_init<<<(N_NODES + 255) / 256, 256>>>(bbuf);
    k_convert<<<(N_EDGES + 255) / 256, 256>>>(ebuf);
    k_scan<<<1, 1024>>>();
    k_scatter<<<(N_EDGES + 255) / 256, 256>>>();

    dim3 gblk(64, 4);
    // layer 1
    k_gemm<<<N_NODES / 32, gblk, smem1>>>(x, W1, as1, ad1, hA, esrc, edst, F_IN);
    k_agg<<<N_NODES / 8, 256>>>(hA, esrc, edst, b1, hB, 1);
    // layer 2
    k_gemm<<<N_NODES / 32, gblk, smem2>>>(hB, W2, as2, ad2, hA, esrc, edst, HID);
    k_agg<<<N_NODES / 8, 256>>>(hA, esrc, edst, b2, hB, 1);
    // layer 3
    k_gemm<<<N_NODES / 32, gblk, smem2>>>(hB, W3, as3, ad3, hA, esrc, edst, HID);
    k_agg<<<N_NODES / 8, 256>>>(hA, esrc, edst, b3, hB, 0);

    // pooling + classifier
    k_pool<<<(N_NODES * 32 + 255) / 256, 256>>>();
    k_final<<<NGRAPH, 32>>>(WL, bl, out);
}

// round 11
// speedup vs baseline: 1.0021x; 1.0021x over previous
#include <cuda_runtime.h>
#include <cuda_bf16.h>
#include <stdint.h>

#define N_NODES 100000
#define N_EDGES 1600000
#define M_TOT   (N_EDGES + N_NODES)
#define F_IN    128
#define HID     64
#define NCLS    10
#define NGRAPH  128

// ---------------- device scratch (no allocation allowed) ----------------
__device__ int   g_src[N_EDGES];
__device__ int   g_dst[N_EDGES];
__device__ int   g_deg[N_NODES];
__device__ int   g_rowptr[N_NODES + 1];
__device__ int   g_offs[N_NODES];
__device__ int   g_csr_src[N_EDGES];
__device__ int   g_batch[N_NODES];
__device__ float g_hA[N_NODES * HID];   // gemm output (messages h)
__device__ float g_hB[N_NODES * HID];   // aggregated output
__device__ float g_esrc[N_NODES];
__device__ float g_edst[N_NODES];
__device__ float g_ex[M_TOT];
__device__ float g_pool[NGRAPH * HID];
__device__ float g_cnt[NGRAPH];
__device__ int   g_flags[2];            // [0]: edge idx is int32, [1]: batch is int32

// ---------------- dtype sniffer ----------------
// int64 little-endian values < 2^31 have zero high words at odd 32-bit indices.
// For batch (sorted, starts at 0) probe the tail where values ~ 127.
__global__ void k_detect(const unsigned* __restrict__ ew, const unsigned* __restrict__ bw) {
    int t = threadIdx.x;
    int ae = 0, ab = 0;
    for (int i = t; i < 1024; i += 256) {
        if (ew[2 * i + 1]) ae = 1;
        int w = (N_NODES - 2048) + 2 * i + 1;      // odd, < N_NODES words (safe both dtypes)
        if (bw[w]) ab = 1;
    }
    int e32 = __syncthreads_or(ae);
    int b32 = __syncthreads_or(ab);
    if (t == 0) { g_flags[0] = e32 ? 1 : 0; g_flags[1] = b32 ? 1 : 0; }
}

// zero deg/pool/cnt + convert batch
__global__ void k_init(const void* __restrict__ bbuf) {
    int i = blockIdx.x * blockDim.x + threadIdx.x;
    if (i >= N_NODES) return;
    g_deg[i] = 0;
    g_batch[i] = g_flags[1] ? ((const int*)bbuf)[i]
                            : (int)((const long long*)bbuf)[i];
    if (i < NGRAPH * HID) g_pool[i] = 0.f;
    if (i < NGRAPH)       g_cnt[i]  = 0.f;
}

__global__ void k_convert(const void* __restrict__ ebuf) {
    int e = blockIdx.x * blockDim.x + threadIdx.x;
    if (e >= N_EDGES) return;
    int s, d;
    if (g_flags[0]) {
        const int* p = (const int*)ebuf;
        s = p[e]; d = p[N_EDGES + e];
    } else {
        const long long* p = (const long long*)ebuf;
        s = (int)p[e]; d = (int)p[N_EDGES + e];
    }
    g_src[e] = s; g_dst[e] = d;
    atomicAdd(&g_deg[d], 1);
}

__global__ void k_scan() {
    const int CH = (N_NODES + 1023) / 1024;      // 98
    int t = threadIdx.x;
    int lo = t * CH, hi = min(lo + CH, N_NODES);
    int s = 0;
    for (int i = lo; i < hi; i++) s += g_deg[i];
    __shared__ int sc[1024];
    sc[t] = s; __syncthreads();
    for (int off = 1; off < 1024; off <<= 1) {
        int v = (t >= off) ? sc[t - off] : 0;
        __syncthreads();
        sc[t] += v;
        __syncthreads();
    }
    int run = (t > 0) ? sc[t - 1] : 0;
    for (int i = lo; i < hi; i++) {
        g_rowptr[i] = run; g_offs[i] = run;
        run += g_deg[i];
    }
    if (t == 1023) g_rowptr[N_NODES] = sc[1023];
}

__global__ void k_scatter() {
    int e = blockIdx.x * blockDim.x + threadIdx.x;
    if (e >= N_EDGES) return;
    int d = g_dst[e];
    int pos = atomicAdd(&g_offs[d], 1);
    g_csr_src[pos] = g_src[e];
}

// ---------------- GEMM: H[n,k] = sum_f X[n,f] W[k,f]; also e_src/e_dst ----
// blockDim (64,4): tx = output column k, each thread handles 8 rows.
// 32 rows per block, grid = N/32 (exact).
__global__ void k_gemm(const float* __restrict__ X, const float* __restrict__ W,
                       const float* __restrict__ a_s, const float* __restrict__ a_d,
                       float* __restrict__ Hout, float* __restrict__ esrc,
                       float* __restrict__ edst, int Fin) {
    extern __shared__ float sm[];
    float* W_s = sm;                     // [64][Fin+4]
    float* xs  = sm + 64 * (Fin + 4);    // [32][Fin]
    const int tx = threadIdx.x, ty = threadIdx.y;
    const int tid = ty * 64 + tx;
    const int row0 = blockIdx.x * 32;

    for (int idx = tid; idx < 64 * Fin; idx += 256) {
        int k = idx / Fin, f = idx - k * Fin;
        W_s[k * (Fin + 4) + f] = W[idx];
    }
    for (int idx = tid; idx < 32 * Fin; idx += 256)
        xs[idx] = X[row0 * Fin + idx];
    __syncthreads();

    const float4* Wv = (const float4*)(W_s + tx * (Fin + 4));
    float acc[8];
#pragma unroll
    for (int j = 0; j < 8; j++) acc[j] = 0.f;

    const int F4 = Fin >> 2;
    for (int f4 = 0; f4 < F4; f4++) {
        float4 w = Wv[f4];
#pragma unroll
        for (int j = 0; j < 8; j++) {
            float4 xv = ((const float4*)(xs + (ty * 8 + j) * Fin))[f4];
            acc[j] += xv.x * w.x + xv.y * w.y + xv.z * w.z + xv.w * w.w;
        }
    }

    const float as = a_s[tx], ad = a_d[tx];
    __shared__ float s_ps[32][2], s_pd[32][2];
    const unsigned FULL = 0xffffffffu;
    const int lane = tx & 31, half = tx >> 5;
#pragma unroll
    for (int j = 0; j < 8; j++) {
        int r = ty * 8 + j;
        float ps = acc[j] * as, pd = acc[j] * ad;
#pragma unroll
        for (int o = 16; o; o >>= 1) {
            ps += __shfl_xor_sync(FULL, ps, o);
            pd += __shfl_xor_sync(FULL, pd, o);
        }
        if (lane == 0) { s_ps[r][half] = ps; s_pd[r][half] = pd; }
        Hout[(row0 + r) * HID + tx] = acc[j];
    }
    __syncthreads();
    if (tid < 32)       esrc[row0 + tid]        = s_ps[tid][0] + s_ps[tid][1];
    else if (tid < 64)  edst[row0 + tid - 32]   = s_pd[tid - 32][0] + s_pd[tid - 32][1];
}

// ---------------- fused per-node aggregation (warp per node) ----------------
__global__ void k_agg(const float* __restrict__ Hn, const float* __restrict__ esrc,
                      const float* __restrict__ edst, const float* __restrict__ bias,
                      float* __restrict__ Out, int do_relu) {
    const unsigned FULL = 0xffffffffu;
    const int warp = threadIdx.x >> 5, lane = threadIdx.x & 31;
    const int n = blockIdx.x * 8 + warp;
    const int start = g_rowptr[n], end = g_rowptr[n + 1];
    const int cnt = end - start + 1;                 // + self loop
    const float ed = edst[n];

    // pass 1: scores + max
    float m = -1e30f;
    for (int i = lane; i < cnt; i += 32) {
        int s = (i == cnt - 1) ? n : g_csr_src[start + i];
        float e = esrc[s] + ed;
        e = (e > 0.f) ? e : 0.2f * e;                // leaky relu 0.2
        g_ex[(i == cnt - 1) ? (N_EDGES + n) : (start + i)] = e;
        m = fmaxf(m, e);
    }
#pragma unroll
    for (int o = 16; o; o >>= 1) m = fmaxf(m, __shfl_xor_sync(FULL, m, o));

    // pass 2: exp + sum
    float sum = 0.f;
    for (int i = lane; i < cnt; i += 32) {
        int pos = (i == cnt - 1) ? (N_EDGES + n) : (start + i);
        float v = __expf(g_ex[pos] - m);
        g_ex[pos] = v;
        sum += v;
    }
#pragma unroll
    for (int o = 16; o; o >>= 1) sum += __shfl_xor_sync(FULL, sum, o);
    const float inv = 1.f / sum;

    // pass 3: weighted accumulation, lane owns 2 features
    float ax = 0.f, ay = 0.f;
    for (int base = 0; base < cnt; base += 32) {
        int i = base + lane;
        float v = 0.f; int s = n;
        if (i < cnt) {
            int pos = (i == cnt - 1) ? (N_EDGES + n) : (start + i);
            v = g_ex[pos];
            if (i < cnt - 1) s = g_csr_src[start + i];
        }
        int lim = min(32, cnt - base);
        for (int j = 0; j < lim; j++) {
            float a = __shfl_sync(FULL, v, j);
            int  sj = __shfl_sync(FULL, s, j);
            float2 hv = *(const float2*)(Hn + sj * HID + lane * 2);
            ax += a * hv.x;
            ay += a * hv.y;
        }
    }
    float2 o;
    o.x = ax * inv + bias[lane * 2];
    o.y = ay * inv + bias[lane * 2 + 1];
    if (do_relu) { o.x = fmaxf(o.x, 0.f); o.y = fmaxf(o.y, 0.f); }
    *(float2*)(Out + n * HID + lane * 2) = o;
}

// ---------------- pooling + final linear ----------------
__global__ void k_pool() {
    int idx = blockIdx.x * blockDim.x + threadIdx.x;   // N*32 threads
    int n = idx >> 5, lane = idx & 31;
    if (n >= N_NODES) return;
    int b = g_batch[n];
    float2 hv = *(const float2*)(g_hB + n * HID + lane * 2);
    atomicAdd(&g_pool[b * HID + lane * 2], hv.x);
    atomicAdd(&g_pool[b * HID + lane * 2 + 1], hv.y);
    if (lane == 0) atomicAdd(&g_cnt[b], 1.f);
}

__global__ void k_final(const float* __restrict__ WL, const float* __restrict__ bl,
                        float* __restrict__ out) {
    const unsigned FULL = 0xffffffffu;
    int b = blockIdx.x, lane = threadIdx.x;
    float c = fmaxf(g_cnt[b], 1.f);
    float inv = 1.f / c;
    float v0 = g_pool[b * HID + lane] * inv;
    float v1 = g_pool[b * HID + 32 + lane] * inv;
    for (int ci = 0; ci < NCLS; ci++) {
        float p = v0 * WL[ci * HID + lane] + v1 * WL[ci * HID + 32 + lane];
#pragma unroll
        for (int o = 16; o; o >>= 1) p += __shfl_xor_sync(FULL, p, o);
        if (lane == 0) out[b * NCLS + ci] = p + bl[ci];
    }
}

// ---------------- launch ----------------
extern "C" void kernel_launch(void* const* d_in, const int* in_sizes, int n_in,
                              void* d_out, int out_size) {
    const float* x     = (const float*)d_in[0];
    const void*  ebuf  = d_in[1];
    const void*  bbuf  = d_in[2];
    const float* W1    = (const float*)d_in[3];
    const float* as1   = (const float*)d_in[4];
    const float* ad1   = (const float*)d_in[5];
    const float* b1    = (const float*)d_in[6];
    const float* W2    = (const float*)d_in[7];
    const float* as2   = (const float*)d_in[8];
    const float* ad2   = (const float*)d_in[9];
    const float* b2    = (const float*)d_in[10];
    const float* W3    = (const float*)d_in[11];
    const float* as3   = (const float*)d_in[12];
    const float* ad3   = (const float*)d_in[13];
    const float* b3    = (const float*)d_in[14];
    const float* WL    = (const float*)d_in[15];
    const float* bl    = (const float*)d_in[16];
    float* out = (float*)d_out;

    float *hA, *hB, *esrc, *edst;
    cudaGetSymbolAddress((void**)&hA,   g_hA);
    cudaGetSymbolAddress((void**)&hB,   g_hB);
    cudaGetSymbolAddress((void**)&esrc, g_esrc);
    cudaGetSymbolAddress((void**)&edst, g_edst);

    size_t smem1 = (size_t)(64 * (F_IN + 4) + 32 * F_IN) * 4;   // 50176 B
    size_t smem2 = (size_t)(64 * (HID + 4) + 32 * HID) * 4;     // 25600 B
    static int attr_set = 0;
    if (!attr_set) {
        cudaFuncSetAttribute(k_gemm, cudaFuncAttributeMaxDynamicSharedMemorySize, 65536);
        attr_set = 1;
    }

    // graph preprocessing
    k_detect<<<1, 256>>>((const unsigned*)ebuf, (const unsigned*)bbuf);
    k_init<<<(N_NODES + 255) / 256, 256>>>(bbuf);
    k_convert<<<(N_EDGES + 255) / 256, 256>>>(ebuf);
    k_scan<<<1, 1024>>>();
    k_scatter<<<(N_EDGES + 255) / 256, 256>>>();

    dim3 gblk(64, 4);
    // layer 1
    k_gemm<<<N_NODES / 32, gblk, smem1>>>(x, W1, as1, ad1, hA, esrc, edst, F_IN);
    k_agg<<<N_NODES / 8, 256>>>(hA, esrc, edst, b1, hB, 1);
    // layer 2
    k_gemm<<<N_NODES / 32, gblk, smem2>>>(hB, W2, as2, ad2, hA, esrc, edst, HID);
    k_agg<<<N_NODES / 8, 256>>>(hA, esrc, edst, b2, hB, 1);
    // layer 3
    k_gemm<<<N_NODES / 32, gblk, smem2>>>(hB, W3, as3, ad3, hA, esrc, edst, HID);
    k_agg<<<N_NODES / 8, 256>>>(hA, esrc, edst, b3, hB, 0);

    // pooling + classifier
    k_pool<<<(N_NODES * 32 + 255) / 256, 256>>>();
    k_final<<<NGRAPH, 32>>>(WL, bl, out);
}